// round 8
// baseline (speedup 1.0000x reference)
#include <cuda_runtime.h>
#include <cuda_bf16.h>
#include <math.h>

#define B_ 4
#define S_ 2048
#define DIN 2048
#define DOUT 2048
#define DEPTH 11
#define NLEV (DEPTH + 1)          // 12
#define NNODES 4095
#define NTOK (B_ * S_)            // 8192
#define NLEAF 2048
#define LEAF0 2047

#define TRN_BX 128                // ceil(4095/32)

// accum config
#define TPC 4                     // tokens per CTA
#define HSZ 64                    // node hash table size (union <= 48)

// Static scratch
__device__ float          g_wout_t[(size_t)NNODES * DOUT];
__device__ float          g_gel[NTOK * NLEV];
__device__ unsigned short g_leaf[NTOK];
__device__ int            g_hist[NLEAF];     // zero-init; re-zeroed by scan_scatter
__device__ int            g_perm[NTOK];

__device__ __forceinline__ float gelu_exact(float s) {
    return 0.5f * s * (1.0f + erff(s * 0.70710678118654752440f));
}

// ---------------------------------------------------------------------------
// Fused: even blocks = traverse (1 token per 64-thread CTA: 2 warps x 1024
// dims, 8 float4 x-regs/lane, 8-deep load MLP); odd blocks = transpose w_out.
// ---------------------------------------------------------------------------
__global__ __launch_bounds__(64) void fused_traverse_kernel(
    const float* __restrict__ x,
    const float* __restrict__ w_in,
    const float* __restrict__ w_out)
{
    __shared__ float tile[32][33];
    __shared__ float part[2][2];          // [level parity][half]

    if (blockIdx.x & 1) {
        // ---- transpose partition: w_out [DOUT,NNODES] -> g_wout_t ----
        const int tb  = blockIdx.x >> 1;
        const int nx0 = (tb % TRN_BX) * 32;
        const int dy0 = (tb / TRN_BX) * 32;
        const int tx  = threadIdx.x & 31;
        const int ty  = threadIdx.x >> 5;          // 0..1
#pragma unroll
        for (int j = 0; j < 32; j += 2) {
            int r = dy0 + ty + j, c = nx0 + tx;
            float v = 0.f;
            if (c < NNODES) v = w_out[(size_t)r * NNODES + c];
            tile[ty + j][tx] = v;
        }
        __syncthreads();
#pragma unroll
        for (int j = 0; j < 32; j += 2) {
            int r = nx0 + ty + j, c = dy0 + tx;
            if (r < NNODES) g_wout_t[(size_t)r * DOUT + c] = tile[tx][ty + j];
        }
        return;
    }

    // ---- traverse partition ----
    const int tok  = blockIdx.x >> 1;
    const int h    = threadIdx.x >> 5;             // half 0/1 (1024 dims each)
    const int lane = threadIdx.x & 31;

    const float4* __restrict__ xq =
        reinterpret_cast<const float4*>(x + (size_t)tok * DIN) + h * 256;
    float4 xr[8];
#pragma unroll
    for (int j = 0; j < 8; j++) xr[j] = xq[j * 32 + lane];

    const float4* __restrict__ wb =
        reinterpret_cast<const float4*>(w_in) + h * 256;

    int cur = 0;
#pragma unroll
    for (int l = 0; l < NLEV; l++) {
        const float4* __restrict__ w = wb + (size_t)cur * 512;
        float4 a[8];
#pragma unroll
        for (int j = 0; j < 8; j++) a[j] = w[j * 32 + lane];   // 8-deep MLP

        float p0 = 0.f, p1 = 0.f, p2 = 0.f, p3 = 0.f;
#pragma unroll
        for (int j = 0; j < 8; j += 4) {
            p0 += xr[j+0].x * a[j+0].x + xr[j+0].y * a[j+0].y
                + xr[j+0].z * a[j+0].z + xr[j+0].w * a[j+0].w;
            p1 += xr[j+1].x * a[j+1].x + xr[j+1].y * a[j+1].y
                + xr[j+1].z * a[j+1].z + xr[j+1].w * a[j+1].w;
            p2 += xr[j+2].x * a[j+2].x + xr[j+2].y * a[j+2].y
                + xr[j+2].z * a[j+2].z + xr[j+2].w * a[j+2].w;
            p3 += xr[j+3].x * a[j+3].x + xr[j+3].y * a[j+3].y
                + xr[j+3].z * a[j+3].z + xr[j+3].w * a[j+3].w;
        }
        float p = (p0 + p1) + (p2 + p3);
#pragma unroll
        for (int off = 16; off > 0; off >>= 1)
            p += __shfl_xor_sync(0xffffffffu, p, off);

        if (lane == 0) part[l & 1][h] = p;
        __syncthreads();
        const float s = part[l & 1][0] + part[l & 1][1];
        if (threadIdx.x == 0) g_gel[tok * NLEV + l] = gelu_exact(s);
        cur = cur * 2 + 1 + (s >= 0.0f ? 1 : 0);
    }
    if (threadIdx.x == 0) {
        const int leaf = ((cur - 1) >> 1) - LEAF0;
        g_leaf[tok] = (unsigned short)leaf;
        atomicAdd(&g_hist[leaf], 1);
    }
}

// ---------------------------------------------------------------------------
// Fused scan + scatter, one CTA of 1024 threads. Re-zeroes g_hist for the
// next graph replay (statics start zeroed for the first call).
// ---------------------------------------------------------------------------
__global__ __launch_bounds__(1024) void scan_scatter_kernel() {
    __shared__ int s0[NLEAF];
    __shared__ int s1[NLEAF];
    const int t = threadIdx.x;
    s0[t]        = g_hist[t];
    s0[t + 1024] = g_hist[t + 1024];
    g_hist[t]        = 0;
    g_hist[t + 1024] = 0;
    __syncthreads();
    int* src = s0; int* dst = s1;
    for (int off = 1; off < NLEAF; off <<= 1) {
#pragma unroll
        for (int k = 0; k < 2; k++) {
            int i = t + k * 1024;
            int v = src[i];
            if (i >= off) v += src[i - off];
            dst[i] = v;
        }
        __syncthreads();
        int* tmp = src; src = dst; dst = tmp;
    }
#pragma unroll
    for (int k = 0; k < 2; k++) {
        int i = t + k * 1024;
        dst[i] = (i == 0) ? 0 : src[i - 1];
    }
    __syncthreads();
#pragma unroll
    for (int k = 0; k < 8; k++) {
        int tok  = t + k * 1024;
        int leaf = (int)g_leaf[tok];
        int pos  = atomicAdd(&dst[leaf], 1);
        g_perm[pos] = tok;
    }
}

// ---------------------------------------------------------------------------
// Accumulate: 512-thread CTA = 4 leaf-sorted tokens; thread owns ONE float4.
// acc = 4 x float4 = 16 regs. Union of 4 paths loaded once, FFMA into all 4.
// ---------------------------------------------------------------------------
__global__ __launch_bounds__(512, 3) void accum_kernel(float* __restrict__ out) {
    __shared__ int   s_key[HSZ];
    __shared__ float s_gl[HSZ][TPC];
    __shared__ int   s_list[HSZ];
    __shared__ int   s_cnt;
    __shared__ int   s_tok[TPC];
    __shared__ int   s_leafp1[TPC];

    const int tid = threadIdx.x;

    if (tid < HSZ) s_key[tid] = -1;
    if (tid < HSZ * TPC) (&s_gl[0][0])[tid] = 0.0f;
    if (tid == 0) s_cnt = 0;
    if (tid < TPC) {
        int tk = g_perm[blockIdx.x * TPC + tid];
        s_tok[tid]    = tk;
        s_leafp1[tid] = ((int)g_leaf[tk] + LEAF0) + 1;
    }
    __syncthreads();

    if (tid < TPC * NLEV) {
        const int t = tid / NLEV;
        const int l = tid % NLEV;
        const int node = (s_leafp1[t] >> (DEPTH - l)) - 1;
        const float gl = g_gel[s_tok[t] * NLEV + l];
        unsigned slot = ((unsigned)node * 2654435761u >> 16) & (HSZ - 1);
        while (true) {
            int prev = atomicCAS(&s_key[slot], -1, node);
            if (prev == -1 || prev == node) break;
            slot = (slot + 1) & (HSZ - 1);
        }
        s_gl[slot][t] = gl;
    }
    __syncthreads();

    if (tid < HSZ) {
        if (s_key[tid] != -1) {
            int pos = atomicAdd(&s_cnt, 1);
            s_list[pos] = tid;
        }
    }
    __syncthreads();
    const int cnt = s_cnt;

    float4 acc[TPC];
#pragma unroll
    for (int t = 0; t < TPC; t++) acc[t] = make_float4(0.f, 0.f, 0.f, 0.f);

    for (int i = 0; i < cnt; i++) {
        const int slot = s_list[i];
        const int node = s_key[slot];
        const float4 r =
            reinterpret_cast<const float4*>(g_wout_t + (size_t)node * DOUT)[tid];
        float gl[TPC];
#pragma unroll
        for (int t = 0; t < TPC; t++) gl[t] = s_gl[slot][t];
#pragma unroll
        for (int t = 0; t < TPC; t++) {
            acc[t].x += gl[t] * r.x;
            acc[t].y += gl[t] * r.y;
            acc[t].z += gl[t] * r.z;
            acc[t].w += gl[t] * r.w;
        }
    }

#pragma unroll
    for (int t = 0; t < TPC; t++)
        reinterpret_cast<float4*>(out + (size_t)s_tok[t] * DOUT)[tid] = acc[t];
}

// ---------------------------------------------------------------------------
extern "C" void kernel_launch(void* const* d_in, const int* in_sizes, int n_in,
                              void* d_out, int out_size) {
    const float* x     = (const float*)d_in[0];
    const float* w_in  = (const float*)d_in[1];
    const float* w_out = (const float*)d_in[2];
    float* out = (float*)d_out;

    fused_traverse_kernel<<<2 * NTOK, 64>>>(x, w_in, w_out);   // even=traverse, odd=transpose
    scan_scatter_kernel<<<1, 1024>>>();
    accum_kernel<<<NTOK / TPC, 512>>>(out);
}

// round 9
// speedup vs baseline: 1.1939x; 1.1939x over previous
#include <cuda_runtime.h>
#include <cuda_bf16.h>
#include <math.h>

#define B_ 4
#define S_ 2048
#define DIN 2048
#define DOUT 2048
#define DEPTH 11
#define NLEV (DEPTH + 1)          // 12
#define NNODES 4095
#define NTOK (B_ * S_)            // 8192
#define NLEAF 2048
#define LEAF0 2047

#define TRN_BX 128                // ceil(4095/32)

// accum config
#define TPC 8                     // tokens per CTA
#define HSZ 128                   // node hash table size (union <= 96)

// Static scratch
__device__ float          g_wout_t[(size_t)NNODES * DOUT];
__device__ float          g_gel[NTOK * NLEV];
__device__ unsigned short g_leaf[NTOK];
__device__ int            g_hist[NLEAF];     // zero-init; re-zeroed by scan_scatter
__device__ int            g_perm[NTOK];

__device__ __forceinline__ float gelu_exact(float s) {
    return 0.5f * s * (1.0f + erff(s * 0.70710678118654752440f));
}

// ---------------------------------------------------------------------------
// Fused: even blocks = traverse (1 token per 128-thread CTA, 4 warps x 512
// dims — the R5 winning config); odd blocks = transpose w_out.
// Cache policy: levels 0-4 (31 nodes, ~248KB ~= L1) use default caching;
// levels 5-11 (32MB working set) bypass L1 with __ldcg to stop thrashing.
// ---------------------------------------------------------------------------
__global__ __launch_bounds__(128) void fused_traverse_kernel(
    const float* __restrict__ x,
    const float* __restrict__ w_in,
    const float* __restrict__ w_out)
{
    __shared__ float tile[32][33];
    __shared__ float part[2][4];

    if (blockIdx.x & 1) {
        // ---- transpose partition: w_out [DOUT,NNODES] -> g_wout_t ----
        const int tb  = blockIdx.x >> 1;
        const int nx0 = (tb % TRN_BX) * 32;
        const int dy0 = (tb / TRN_BX) * 32;
        const int tx  = threadIdx.x & 31;
        const int ty  = threadIdx.x >> 5;          // 0..3
#pragma unroll
        for (int j = 0; j < 32; j += 4) {
            int r = dy0 + ty + j, c = nx0 + tx;
            float v = 0.f;
            if (c < NNODES) v = w_out[(size_t)r * NNODES + c];
            tile[ty + j][tx] = v;
        }
        __syncthreads();
#pragma unroll
        for (int j = 0; j < 32; j += 4) {
            int r = nx0 + ty + j, c = dy0 + tx;
            if (r < NNODES) g_wout_t[(size_t)r * DOUT + c] = tile[tx][ty + j];
        }
        return;
    }

    // ---- traverse partition: 4 warps x 512 dims, one token ----
    const int tok  = blockIdx.x >> 1;
    const int q    = threadIdx.x >> 5;
    const int lane = threadIdx.x & 31;

    const float4* __restrict__ xq =
        reinterpret_cast<const float4*>(x + (size_t)tok * DIN) + q * 128;
    float4 xr[4];
#pragma unroll
    for (int j = 0; j < 4; j++) xr[j] = xq[j * 32 + lane];

    const float4* __restrict__ wb =
        reinterpret_cast<const float4*>(w_in) + q * 128;

    int cur = 0;
#pragma unroll
    for (int l = 0; l < NLEV; l++) {
        const float4* __restrict__ w = wb + (size_t)cur * 512;
        float4 a, b, c, d;
        if (l < 5) {                       // shallow: keep in L1 (high reuse)
            a = w[0 * 32 + lane];
            b = w[1 * 32 + lane];
            c = w[2 * 32 + lane];
            d = w[3 * 32 + lane];
        } else {                           // deep: L2-only, don't thrash L1
            a = __ldcg(&w[0 * 32 + lane]);
            b = __ldcg(&w[1 * 32 + lane]);
            c = __ldcg(&w[2 * 32 + lane]);
            d = __ldcg(&w[3 * 32 + lane]);
        }
        float p0 = xr[0].x * a.x + xr[0].y * a.y + xr[0].z * a.z + xr[0].w * a.w;
        float p1 = xr[1].x * b.x + xr[1].y * b.y + xr[1].z * b.z + xr[1].w * b.w;
        float p2 = xr[2].x * c.x + xr[2].y * c.y + xr[2].z * c.z + xr[2].w * c.w;
        float p3 = xr[3].x * d.x + xr[3].y * d.y + xr[3].z * d.z + xr[3].w * d.w;
        float p = (p0 + p1) + (p2 + p3);
#pragma unroll
        for (int off = 16; off > 0; off >>= 1)
            p += __shfl_xor_sync(0xffffffffu, p, off);
        if (lane == 0) part[l & 1][q] = p;
        __syncthreads();
        const float s = (part[l & 1][0] + part[l & 1][1])
                      + (part[l & 1][2] + part[l & 1][3]);
        if (threadIdx.x == 0) g_gel[tok * NLEV + l] = gelu_exact(s);
        cur = cur * 2 + 1 + (s >= 0.0f ? 1 : 0);
    }
    if (threadIdx.x == 0) {
        const int leaf = ((cur - 1) >> 1) - LEAF0;
        g_leaf[tok] = (unsigned short)leaf;
        atomicAdd(&g_hist[leaf], 1);
    }
}

// ---------------------------------------------------------------------------
// Fused scan + scatter, one CTA of 1024 threads. Re-zeroes g_hist for the
// next graph replay (statics start zeroed for the first call).
// ---------------------------------------------------------------------------
__global__ __launch_bounds__(1024) void scan_scatter_kernel() {
    __shared__ int s0[NLEAF];
    __shared__ int s1[NLEAF];
    const int t = threadIdx.x;
    s0[t]        = g_hist[t];
    s0[t + 1024] = g_hist[t + 1024];
    g_hist[t]        = 0;
    g_hist[t + 1024] = 0;
    __syncthreads();
    int* src = s0; int* dst = s1;
    for (int off = 1; off < NLEAF; off <<= 1) {
#pragma unroll
        for (int k = 0; k < 2; k++) {
            int i = t + k * 1024;
            int v = src[i];
            if (i >= off) v += src[i - off];
            dst[i] = v;
        }
        __syncthreads();
        int* tmp = src; src = dst; dst = tmp;
    }
#pragma unroll
    for (int k = 0; k < 2; k++) {
        int i = t + k * 1024;
        dst[i] = (i == 0) ? 0 : src[i - 1];
    }
    __syncthreads();
#pragma unroll
    for (int k = 0; k < 8; k++) {
        int tok  = t + k * 1024;
        int leaf = (int)g_leaf[tok];
        int pos  = atomicAdd(&dst[leaf], 1);
        g_perm[pos] = tok;
    }
}

// ---------------------------------------------------------------------------
// Accumulate (R7 winner): 512-thread CTA = 8 leaf-sorted tokens; thread owns
// ONE float4 of the row; acc = 32 regs -> 2 CTAs/SM. Union of 8 paths loaded
// once per CTA, FFMA into all 8 token accumulators.
// ---------------------------------------------------------------------------
__global__ __launch_bounds__(512, 2) void accum_kernel(float* __restrict__ out) {
    __shared__ int   s_key[HSZ];
    __shared__ float s_gl[HSZ][TPC];
    __shared__ int   s_list[HSZ];
    __shared__ int   s_cnt;
    __shared__ int   s_tok[TPC];
    __shared__ int   s_leafp1[TPC];

    const int tid = threadIdx.x;

    if (tid < HSZ) s_key[tid] = -1;
#pragma unroll
    for (int k = tid; k < HSZ * TPC; k += 512) (&s_gl[0][0])[k] = 0.0f;
    if (tid == 0) s_cnt = 0;
    if (tid < TPC) {
        int tk = g_perm[blockIdx.x * TPC + tid];
        s_tok[tid]    = tk;
        s_leafp1[tid] = ((int)g_leaf[tk] + LEAF0) + 1;
    }
    __syncthreads();

    if (tid < TPC * NLEV) {
        const int t = tid / NLEV;
        const int l = tid % NLEV;
        const int node = (s_leafp1[t] >> (DEPTH - l)) - 1;
        const float gl = g_gel[s_tok[t] * NLEV + l];
        unsigned slot = ((unsigned)node * 2654435761u >> 16) & (HSZ - 1);
        while (true) {
            int prev = atomicCAS(&s_key[slot], -1, node);
            if (prev == -1 || prev == node) break;
            slot = (slot + 1) & (HSZ - 1);
        }
        s_gl[slot][t] = gl;
    }
    __syncthreads();

    if (tid < HSZ) {
        if (s_key[tid] != -1) {
            int pos = atomicAdd(&s_cnt, 1);
            s_list[pos] = tid;
        }
    }
    __syncthreads();
    const int cnt = s_cnt;

    float4 acc[TPC];
#pragma unroll
    for (int t = 0; t < TPC; t++) acc[t] = make_float4(0.f, 0.f, 0.f, 0.f);

    for (int i = 0; i < cnt; i++) {
        const int slot = s_list[i];
        const int node = s_key[slot];
        const float4 r =
            reinterpret_cast<const float4*>(g_wout_t + (size_t)node * DOUT)[tid];
        float gl[TPC];
#pragma unroll
        for (int t = 0; t < TPC; t++) gl[t] = s_gl[slot][t];
#pragma unroll
        for (int t = 0; t < TPC; t++) {
            acc[t].x += gl[t] * r.x;
            acc[t].y += gl[t] * r.y;
            acc[t].z += gl[t] * r.z;
            acc[t].w += gl[t] * r.w;
        }
    }

#pragma unroll
    for (int t = 0; t < TPC; t++)
        reinterpret_cast<float4*>(out + (size_t)s_tok[t] * DOUT)[tid] = acc[t];
}

// ---------------------------------------------------------------------------
extern "C" void kernel_launch(void* const* d_in, const int* in_sizes, int n_in,
                              void* d_out, int out_size) {
    const float* x     = (const float*)d_in[0];
    const float* w_in  = (const float*)d_in[1];
    const float* w_out = (const float*)d_in[2];
    float* out = (float*)d_out;

    fused_traverse_kernel<<<2 * NTOK, 128>>>(x, w_in, w_out);  // even=traverse, odd=transpose
    scan_scatter_kernel<<<1, 1024>>>();
    accum_kernel<<<NTOK / TPC, 512>>>(out);
}